// round 16
// baseline (speedup 1.0000x reference)
#include <cuda_runtime.h>
#include <cuda_bf16.h>
#include <math.h>
#include <stdint.h>

#define TPB 128
#define STATE 24
#define MEMN 10
#define NLAY 3
#define QSTR 196

// smem float offsets
#define XH_F 0          // x-hi bf16 [48][64] swizzled (6144 B)
#define XL_F 1536
#define BIG_F 3072      // qkv f32 [35][196]=6860 ; FF hidden images hh0,hh1,hl0,hl1 (4x6144B) overlap
#define YS_F 9936       // residual f32 [48][64]
#define SMEM_FLOATS 13024
#define SMEM_BYTES (SMEM_FLOATS * 4)

static __device__ float g_base[STATE * 64];
static __device__ uint4 g_qkvF[NLAY * 4 * 24 * 32];      // [l][kt][nt][lane]
static __device__ uint4 g_woF[NLAY * 4 * 8 * 32];
static __device__ uint4 g_w1F[NLAY * 8 * 4 * 8 * 32];    // [l][ct][kt][nt][lane]
static __device__ uint4 g_w2F[NLAY * 8 * 4 * 8 * 32];

__device__ __forceinline__ uint32_t smem_u32(const void* p) {
    uint32_t a;
    asm("{ .reg .u64 t; cvta.to.shared.u64 t, %1; cvt.u32.u64 %0, t; }" : "=r"(a) : "l"(p));
    return a;
}
__device__ __forceinline__ uint32_t pk2(float a, float b) {
    __nv_bfloat162 t = __floats2bfloat162_rn(a, b);
    return *reinterpret_cast<uint32_t*>(&t);
}
__device__ __forceinline__ void split2(float a, float b, uint32_t& h, uint32_t& l) {
    h = pk2(a, b);
    __nv_bfloat162 t = *reinterpret_cast<__nv_bfloat162*>(&h);
    l = pk2(a - __bfloat162float(t.x), b - __bfloat162float(t.y));
}
__device__ __forceinline__ int swb(int row, int col) {
    return row * 128 + (((col >> 3) ^ (row & 7)) << 4) + (col & 7) * 2;
}
__device__ __forceinline__ float gelu_f(float x) {
    return 0.5f * x * (1.0f + erff(x * 0.7071067811865475f));
}
__device__ __forceinline__ void mma_bf16(float* d, const uint32_t* a, uint32_t b0, uint32_t b1) {
    asm volatile(
        "mma.sync.aligned.m16n8k16.row.col.f32.bf16.bf16.f32 "
        "{%0,%1,%2,%3}, {%4,%5,%6,%7}, {%8,%9}, {%0,%1,%2,%3};"
        : "+f"(d[0]), "+f"(d[1]), "+f"(d[2]), "+f"(d[3])
        : "r"(a[0]), "r"(a[1]), "r"(a[2]), "r"(a[3]), "r"(b0), "r"(b1));
}
__device__ __forceinline__ void ldm4(uint32_t* r, uint32_t addr) {
    asm volatile("ldmatrix.sync.aligned.m8n8.x4.shared.b16 {%0,%1,%2,%3}, [%4];"
        : "=r"(r[0]), "=r"(r[1]), "=r"(r[2]), "=r"(r[3]) : "r"(addr));
}

// Warp GEMM over 48 rows (3 mt tiles): D += Xsplit @ Wsplit^T (2-term bf16 split, 3 MMAs).
// A from one 64-col swizzled smem image pair (hi at aH, lo at aL).
template<int NT>
__device__ __forceinline__ void gemm_w(uint32_t aH, uint32_t aL, const uint4* __restrict__ bf,
                                       int nt0, int ntot, float (&acc)[3][NT][4], int lane) {
    const uint32_t ab = (lane & 15) * 128;
    const int hi4 = lane >> 4, sw = lane & 7;
#pragma unroll
    for (int mt = 0; mt < 3; mt++) {
        uint32_t Ah[4][4], Al[4][4];
#pragma unroll
        for (int ks = 0; ks < 4; ks++) {
            uint32_t off = mt * 2048 + ab + (((2 * ks + hi4) ^ sw) << 4);
            ldm4(Ah[ks], aH + off);
            ldm4(Al[ks], aL + off);
        }
#pragma unroll
        for (int j = 0; j < NT; j++) {
#pragma unroll
            for (int ks = 0; ks < 4; ks++) {
                uint4 B = bf[(ks * ntot + nt0 + j) * 32 + lane];
                mma_bf16(acc[mt][j], Ah[ks], B.x, B.y);
                mma_bf16(acc[mt][j], Al[ks], B.x, B.y);
                mma_bf16(acc[mt][j], Ah[ks], B.z, B.w);
            }
        }
    }
}

__device__ __forceinline__ uint4 mkfrag(const float* W, int rs, int n, int k) {
    uint4 r;
    uint32_t h, l;
    split2(W[n * rs + k], W[n * rs + k + 1], h, l);
    r.x = h; r.z = l;
    split2(W[n * rs + k + 8], W[n * rs + k + 9], h, l);
    r.y = h; r.w = l;
    return r;
}

// prep: weight fragments + base embedding
__global__ void prep_kernel(const float* __restrict__ Wqkv, const float* __restrict__ Wo,
                            const float* __restrict__ W1, const float* __restrict__ W2,
                            const int* __restrict__ toks, const float* __restrict__ temb,
                            const float* __restrict__ demb, const float* __restrict__ trait_b,
                            const float* __restrict__ intent_b) {
    int st = gridDim.x * blockDim.x, t0 = blockIdx.x * blockDim.x + threadIdx.x;
    for (int e = t0; e < STATE * 64; e += st) {
        int i = e >> 6, d = e & 63;
        float s = 0.f;
#pragma unroll
        for (int t = 0; t < 8; t++) s += temb[(size_t)toks[i * 8 + t] * 64 + d];
        g_base[e] = s * 0.125f + demb[e] + trait_b[d] + intent_b[d];
    }
    for (int i = t0; i < NLAY * 4 * 24 * 32; i += st) {
        int lane = i & 31, nt = (i >> 5) % 24, kt = (i >> 5) / 24 % 4, l = i / (32 * 24 * 4);
        g_qkvF[i] = mkfrag(Wqkv + l * 192 * 64, 64, nt * 8 + (lane >> 2), kt * 16 + (lane & 3) * 2);
    }
    for (int i = t0; i < NLAY * 4 * 8 * 32; i += st) {
        int lane = i & 31, nt = (i >> 5) % 8, kt = (i >> 5) / 8 % 4, l = i / (32 * 8 * 4);
        g_woF[i] = mkfrag(Wo + l * 64 * 64, 64, nt * 8 + (lane >> 2), kt * 16 + (lane & 3) * 2);
    }
    for (int i = t0; i < NLAY * 8 * 4 * 8 * 32; i += st) {
        int lane = i & 31, nt = (i >> 5) % 8, kt = (i >> 5) / 8 % 4;
        int ct = (i >> 5) / 32 % 8, l = i / (32 * 8 * 4 * 8);
        g_w1F[i] = mkfrag(W1 + l * 512 * 64, 64, ct * 64 + nt * 8 + (lane >> 2),
                          kt * 16 + (lane & 3) * 2);
    }
    for (int i = t0; i < NLAY * 8 * 4 * 8 * 32; i += st) {
        int lane = i & 31, nt = (i >> 5) % 8, kt = (i >> 5) / 8 % 4;
        int ct = (i >> 5) / 32 % 8, l = i / (32 * 8 * 4 * 8);
        g_w2F[i] = mkfrag(W2 + l * 64 * 512, 512, nt * 8 + (lane >> 2),
                          ct * 64 + kt * 16 + (lane & 3) * 2);
    }
}

__device__ __forceinline__ void ln_pass(float* ys, char* xhB, char* xlB,
                                        const float* g, const float* bb, int tid) {
    int w = tid >> 5, lane = tid & 31;
    for (int row = w; row < 48; row += 4) {
        float2 v = ((float2*)ys)[row * 32 + lane];
        float s = v.x + v.y, q = v.x * v.x + v.y * v.y;
#pragma unroll
        for (int off = 16; off; off >>= 1) {
            s += __shfl_xor_sync(0xffffffffu, s, off);
            q += __shfl_xor_sync(0xffffffffu, q, off);
        }
        float mn = s * (1.f / 64.f);
        float rs = rsqrtf(q * (1.f / 64.f) - mn * mn + 1e-5f);
        bool real = row < 35;
        float o0 = real ? (v.x - mn) * rs * g[lane * 2] + bb[lane * 2] : 0.f;
        float o1 = real ? (v.y - mn) * rs * g[lane * 2 + 1] + bb[lane * 2 + 1] : 0.f;
        ((float2*)ys)[row * 32 + lane] = make_float2(o0, o1);
        uint32_t h, l2;
        split2(o0, o1, h, l2);
        int byte = swb(row, lane * 2);
        *(uint32_t*)(xhB + byte) = h;
        *(uint32_t*)(xlB + byte) = l2;
    }
}

__global__ void __launch_bounds__(TPB, 4)
fused_kernel(const float* __restrict__ traits, const float* __restrict__ rel,
             const float* __restrict__ memc, const float* __restrict__ trait_W,
             const float* __restrict__ intent_W, const float* __restrict__ cls,
             const float* __restrict__ bqkv, const float* __restrict__ bo,
             const float* __restrict__ ln1g, const float* __restrict__ ln1b,
             const float* __restrict__ b1, const float* __restrict__ b2,
             const float* __restrict__ ln2g, const float* __restrict__ ln2b,
             const float* __restrict__ outW, const float* __restrict__ outb,
             const float* __restrict__ outlng, const float* __restrict__ outlnb,
             float* __restrict__ out_sit, float* __restrict__ out_seq,
             float* __restrict__ out_mem) {
    extern __shared__ float smem[];
    char* xhB = (char*)(smem + XH_F);
    char* xlB = (char*)(smem + XL_F);
    char* hB  = (char*)(smem + BIG_F);   // hidden: hh0,hh1 (12288B) then hl0,hl1 (12288B)
    float* qkv = smem + BIG_F;
    float* ys  = smem + YS_F;

    const int tid = threadIdx.x;
    const int wid = tid >> 5, lane = tid & 31;
    const uint32_t sb = smem_u32(smem);
    const uint32_t xh_a = sb + XH_F * 4, xl_a = sb + XL_F * 4;
    const uint32_t hh_a = sb + BIG_F * 4;
    const int gb = blockIdx.x;
    const int r0l = lane >> 2, ql = lane & 3;

    // ---- build x: ys float + xh/xl swizzled bf16 (rows >=35 zero) ----
    for (int idx = tid; idx < 48 * 32; idx += TPB) {
        int row = idx >> 5, cp = idx & 31;
        float v[2];
#pragma unroll
        for (int u = 0; u < 2; u++) {
            int d = cp * 2 + u;
            float x = 0.f;
            if (row == 0) x = cls[d];
            else if (row <= STATE) {
                int i = row - 1;
                x = g_base[i * 64 + d]
                    + traits[((size_t)gb * STATE + i) * 2] * trait_W[d * 2]
                    + traits[((size_t)gb * STATE + i) * 2 + 1] * trait_W[d * 2 + 1]
                    + rel[(size_t)gb * STATE + i] * intent_W[d];
            } else if (row < 35) {
                x = memc[((size_t)gb * MEMN + (row - 25)) * 64 + d];
            }
            v[u] = x;
        }
        ((float2*)ys)[row * 32 + cp] = make_float2(v[0], v[1]);
        uint32_t h, l;
        split2(v[0], v[1], h, l);
        int byte = swb(row, cp * 2);
        *(uint32_t*)(xhB + byte) = h;
        *(uint32_t*)(xlB + byte) = l;
    }
    __syncthreads();

    for (int l = 0; l < NLAY; l++) {
        // ======== QKV: each warp covers 48 cols (6 nt) ========
        {
            float acc[3][6][4];
#pragma unroll
            for (int m = 0; m < 3; m++)
#pragma unroll
                for (int j = 0; j < 6; j++)
#pragma unroll
                    for (int c = 0; c < 4; c++) acc[m][j][c] = 0.f;
            gemm_w<6>(xh_a, xl_a, g_qkvF + l * 4 * 24 * 32, wid * 6, 24, acc, lane);
#pragma unroll
            for (int m = 0; m < 3; m++)
#pragma unroll
                for (int j = 0; j < 6; j++) {
                    int row = m * 16 + r0l;
                    int n = (wid * 6 + j) * 8 + ql * 2;
                    float bb0 = bqkv[l * 192 + n], bb1 = bqkv[l * 192 + n + 1];
                    if (row < 35) {
                        qkv[row * QSTR + n]     = acc[m][j][0] + bb0;
                        qkv[row * QSTR + n + 1] = acc[m][j][1] + bb1;
                    }
                    if (row + 8 < 35) {
                        qkv[(row + 8) * QSTR + n]     = acc[m][j][2] + bb0;
                        qkv[(row + 8) * QSTR + n + 1] = acc[m][j][3] + bb1;
                    }
                }
        }
        __syncthreads();
        // ======== attention (float4 loads) -> xh/xl ========
        for (int t = tid; t < 280; t += TPB) {
            int i = t % 35, h = t / 35;
            float4 q0 = *(float4*)(qkv + i * QSTR + h * 8);
            float4 q1 = *(float4*)(qkv + i * QSTR + h * 8 + 4);
            float sc[35];
            float mx = -1e30f;
#pragma unroll
            for (int j = 0; j < 35; j++) {
                float4 k0 = *(float4*)(qkv + j * QSTR + 64 + h * 8);
                float4 k1 = *(float4*)(qkv + j * QSTR + 64 + h * 8 + 4);
                float a = q0.x * k0.x + q0.y * k0.y + q0.z * k0.z + q0.w * k0.w
                        + q1.x * k1.x + q1.y * k1.y + q1.z * k1.z + q1.w * k1.w;
                a *= 0.35355339059327373f;
                sc[j] = a;
                mx = fmaxf(mx, a);
            }
            float sum = 0.f;
#pragma unroll
            for (int j = 0; j < 35; j++) { float e = __expf(sc[j] - mx); sc[j] = e; sum += e; }
            float inv = 1.f / sum;
            float o[8];
#pragma unroll
            for (int d = 0; d < 8; d++) o[d] = 0.f;
#pragma unroll
            for (int j = 0; j < 35; j++) {
                float w = sc[j];
                float4 v0 = *(float4*)(qkv + j * QSTR + 128 + h * 8);
                float4 v1 = *(float4*)(qkv + j * QSTR + 128 + h * 8 + 4);
                o[0] += w * v0.x; o[1] += w * v0.y; o[2] += w * v0.z; o[3] += w * v0.w;
                o[4] += w * v1.x; o[5] += w * v1.y; o[6] += w * v1.z; o[7] += w * v1.w;
            }
#pragma unroll
            for (int d = 0; d < 8; d += 2) {
                uint32_t hh, ll;
                split2(o[d] * inv, o[d + 1] * inv, hh, ll);
                int byte = swb(i, h * 8 + d);
                *(uint32_t*)(xhB + byte) = hh;
                *(uint32_t*)(xlB + byte) = ll;
            }
        }
        __syncthreads();
        // ======== Wo: each warp covers 16 cols ========
        {
            float acc[3][2][4];
#pragma unroll
            for (int m = 0; m < 3; m++)
#pragma unroll
                for (int j = 0; j < 2; j++)
#pragma unroll
                    for (int c = 0; c < 4; c++) acc[m][j][c] = 0.f;
            gemm_w<2>(xh_a, xl_a, g_woF + l * 4 * 8 * 32, wid * 2, 8, acc, lane);
#pragma unroll
            for (int m = 0; m < 3; m++)
#pragma unroll
                for (int j = 0; j < 2; j++) {
                    int row = m * 16 + r0l;
                    int n = (wid * 2 + j) * 8 + ql * 2;
                    float bb0 = bo[l * 64 + n], bb1 = bo[l * 64 + n + 1];
                    ys[row * 64 + n]           += acc[m][j][0] + bb0;
                    ys[row * 64 + n + 1]       += acc[m][j][1] + bb1;
                    ys[(row + 8) * 64 + n]     += acc[m][j][2] + bb0;
                    ys[(row + 8) * 64 + n + 1] += acc[m][j][3] + bb1;
                }
        }
        __syncthreads();
        ln_pass(ys, xhB, xlB, ln1g + l * 64, ln1b + l * 64, tid);
        __syncthreads();
        // ======== FF: 4 chunks of 128 hidden (FF1 NT=4); W2 acc in regs across chunks ========
        {
            float acc2[3][2][4];
#pragma unroll
            for (int m = 0; m < 3; m++)
#pragma unroll
                for (int j = 0; j < 2; j++)
#pragma unroll
                    for (int c = 0; c < 4; c++) acc2[m][j][c] = 0.f;
            for (int cc = 0; cc < 4; cc++) {
                float acc1[3][4][4];
#pragma unroll
                for (int m = 0; m < 3; m++)
#pragma unroll
                    for (int j = 0; j < 4; j++)
#pragma unroll
                        for (int c = 0; c < 4; c++) acc1[m][j][c] = 0.f;
                // warp w covers cols w*32..w*32+31 of the 128-chunk:
                // ct = 2*cc + (wid>>1), nt0 = (wid&1)*4 within that ct (ntot=8)
                gemm_w<4>(xh_a, xl_a, g_w1F + (l * 8 + 2 * cc + (wid >> 1)) * 1024,
                          (wid & 1) * 4, 8, acc1, lane);
#pragma unroll
                for (int m = 0; m < 3; m++) {
#pragma unroll
                    for (int j = 0; j < 4; j++) {
                        int row = m * 16 + r0l;
                        int colin = (wid & 1) * 32 + j * 8 + ql * 2;   // col within 64-img
                        int img = wid >> 1;
                        int bn = l * 512 + cc * 128 + img * 64 + colin;
                        float bb0 = b1[bn], bb1 = b1[bn + 1];
                        uint32_t h, lo2;
                        split2(gelu_f(acc1[m][j][0] + bb0), gelu_f(acc1[m][j][1] + bb1), h, lo2);
                        int byte = img * 6144 + swb(row, colin);
                        *(uint32_t*)(hB + byte) = h;
                        *(uint32_t*)(hB + 12288 + byte) = lo2;
                        split2(gelu_f(acc1[m][j][2] + bb0), gelu_f(acc1[m][j][3] + bb1), h, lo2);
                        byte = img * 6144 + swb(row + 8, colin);
                        *(uint32_t*)(hB + byte) = h;
                        *(uint32_t*)(hB + 12288 + byte) = lo2;
                    }
                }
                __syncthreads();
                // FF2 over the two 64-col hidden images of this chunk
#pragma unroll
                for (int img = 0; img < 2; img++) {
                    gemm_w<2>(hh_a + img * 6144, hh_a + 12288 + img * 6144,
                              g_w2F + (l * 8 + 2 * cc + img) * 1024, wid * 2, 8, acc2, lane);
                }
                __syncthreads();
            }
#pragma unroll
            for (int m = 0; m < 3; m++)
#pragma unroll
                for (int j = 0; j < 2; j++) {
                    int row = m * 16 + r0l;
                    int n = (wid * 2 + j) * 8 + ql * 2;
                    float bb0 = b2[l * 64 + n], bb1 = b2[l * 64 + n + 1];
                    ys[row * 64 + n]           += acc2[m][j][0] + bb0;
                    ys[row * 64 + n + 1]       += acc2[m][j][1] + bb1;
                    ys[(row + 8) * 64 + n]     += acc2[m][j][2] + bb0;
                    ys[(row + 8) * 64 + n + 1] += acc2[m][j][3] + bb1;
                }
        }
        __syncthreads();
        ln_pass(ys, xhB, xlB, ln2g + l * 64, ln2b + l * 64, tid);
        __syncthreads();
    }

    // ---- head: situation = LN128(x[cls] @ outW^T + outb) ----
    {
        int j = tid;
        float a = outb[j];
        const float* wr = outW + j * 64;
#pragma unroll
        for (int k = 0; k < 64; k++) a += ys[k] * wr[k];
        qkv[j] = a;
    }
    __syncthreads();
    if (wid == 0) {
        float v4[4];
        float s = 0.f, q = 0.f;
#pragma unroll
        for (int u = 0; u < 4; u++) {
            float v = qkv[lane * 4 + u];
            v4[u] = v; s += v; q += v * v;
        }
#pragma unroll
        for (int off = 16; off; off >>= 1) {
            s += __shfl_xor_sync(0xffffffffu, s, off);
            q += __shfl_xor_sync(0xffffffffu, q, off);
        }
        float mn = s * (1.f / 128.f);
        float rs = rsqrtf(q * (1.f / 128.f) - mn * mn + 1e-5f);
#pragma unroll
        for (int u = 0; u < 4; u++) {
            int j = lane * 4 + u;
            out_sit[(size_t)gb * 128 + j] = (v4[u] - mn) * rs * outlng[j] + outlnb[j];
        }
    }
    for (int idx = tid; idx < STATE * 64; idx += TPB)
        out_seq[(size_t)gb * STATE * 64 + idx] = ys[(1 + (idx >> 6)) * 64 + (idx & 63)];
    for (int idx = tid; idx < 9 * 64; idx += TPB)
        out_mem[(size_t)gb * 640 + idx] = memc[(size_t)gb * 640 + 64 + idx];
    if (tid < 64) {
        float s = 0.f;
#pragma unroll
        for (int i = 1; i <= STATE; i++) s += ys[i * 64 + tid];
        out_mem[(size_t)gb * 640 + 9 * 64 + tid] = s * (1.f / 24.f);
    }
}

extern "C" void kernel_launch(void* const* d_in, const int* in_sizes, int n_in,
                              void* d_out, int out_size) {
    const int*   toks     = (const int*)d_in[0];
    const float* traits   = (const float*)d_in[1];
    const float* rel      = (const float*)d_in[2];
    const float* memc     = (const float*)d_in[3];
    const float* temb     = (const float*)d_in[4];
    const float* demb     = (const float*)d_in[5];
    const float* trait_W  = (const float*)d_in[6];
    const float* trait_b  = (const float*)d_in[7];
    const float* intent_W = (const float*)d_in[8];
    const float* intent_b = (const float*)d_in[9];
    const float* cls      = (const float*)d_in[10];
    const float* Wqkv     = (const float*)d_in[11];
    const float* bqkv     = (const float*)d_in[12];
    const float* Wo       = (const float*)d_in[13];
    const float* bo       = (const float*)d_in[14];
    const float* ln1g     = (const float*)d_in[15];
    const float* ln1b     = (const float*)d_in[16];
    const float* W1       = (const float*)d_in[17];
    const float* b1       = (const float*)d_in[18];
    const float* W2       = (const float*)d_in[19];
    const float* b2       = (const float*)d_in[20];
    const float* ln2g     = (const float*)d_in[21];
    const float* ln2b     = (const float*)d_in[22];
    const float* outW     = (const float*)d_in[23];
    const float* outb     = (const float*)d_in[24];
    const float* outlng   = (const float*)d_in[25];
    const float* outlnb   = (const float*)d_in[26];

    int B = in_sizes[2] / STATE;
    float* out = (float*)d_out;
    float* out_sit = out;
    float* out_seq = out + (size_t)B * 128;
    float* out_mem = out_seq + (size_t)B * STATE * 64;

    prep_kernel<<<120, 256>>>(Wqkv, Wo, W1, W2, toks, temb, demb, trait_b, intent_b);

    cudaFuncSetAttribute(fused_kernel, cudaFuncAttributeMaxDynamicSharedMemorySize, SMEM_BYTES);
    fused_kernel<<<B, TPB, SMEM_BYTES>>>(
        traits, rel, memc, trait_W, intent_W, cls,
        bqkv, bo, ln1g, ln1b, b1, b2, ln2g, ln2b,
        outW, outb, outlng, outlnb,
        out_sit, out_seq, out_mem);
}

// round 17
// speedup vs baseline: 1.1257x; 1.1257x over previous
#include <cuda_runtime.h>
#include <cuda_bf16.h>
#include <math.h>
#include <stdint.h>

#define TPB 256
#define STATE 24
#define MEMN 10
#define NLAY 3
#define QSTR 196

// smem float offsets
#define XH_F 0          // x-hi bf16 [80][64] swizzled (10240 B)
#define XL_F 2560
#define BIG_F 5120      // qkv f32 [80][196]=15680 ; FF hidden images overlap (hh0,hh1,hl0,hl1)
#define YS_F 20800      // residual f32 [80][64]
#define SMEM_FLOATS 25920
#define SMEM_BYTES (SMEM_FLOATS * 4)

static __device__ float g_base[STATE * 64];
static __device__ uint4 g_qkvF[NLAY * 4 * 24 * 32];      // [l][kt][nt][lane]
static __device__ uint4 g_woF[NLAY * 4 * 8 * 32];
static __device__ uint4 g_w1F[NLAY * 8 * 4 * 8 * 32];    // [l][ct][kt][nt][lane]
static __device__ uint4 g_w2F[NLAY * 8 * 4 * 8 * 32];

__device__ __forceinline__ uint32_t smem_u32(const void* p) {
    uint32_t a;
    asm("{ .reg .u64 t; cvta.to.shared.u64 t, %1; cvt.u32.u64 %0, t; }" : "=r"(a) : "l"(p));
    return a;
}
__device__ __forceinline__ uint32_t pk2(float a, float b) {
    __nv_bfloat162 t = __floats2bfloat162_rn(a, b);
    return *reinterpret_cast<uint32_t*>(&t);
}
__device__ __forceinline__ void split2(float a, float b, uint32_t& h, uint32_t& l) {
    h = pk2(a, b);
    __nv_bfloat162 t = *reinterpret_cast<__nv_bfloat162*>(&h);
    l = pk2(a - __bfloat162float(t.x), b - __bfloat162float(t.y));
}
__device__ __forceinline__ int swb(int row, int col) {
    return row * 128 + (((col >> 3) ^ (row & 7)) << 4) + (col & 7) * 2;
}
__device__ __forceinline__ float gelu_f(float x) {
    return 0.5f * x * (1.0f + erff(x * 0.7071067811865475f));
}
__device__ __forceinline__ void mma_bf16(float* d, const uint32_t* a, uint32_t b0, uint32_t b1) {
    asm volatile(
        "mma.sync.aligned.m16n8k16.row.col.f32.bf16.bf16.f32 "
        "{%0,%1,%2,%3}, {%4,%5,%6,%7}, {%8,%9}, {%0,%1,%2,%3};"
        : "+f"(d[0]), "+f"(d[1]), "+f"(d[2]), "+f"(d[3])
        : "r"(a[0]), "r"(a[1]), "r"(a[2]), "r"(a[3]), "r"(b0), "r"(b1));
}
__device__ __forceinline__ void ldm4(uint32_t* r, uint32_t addr) {
    asm volatile("ldmatrix.sync.aligned.m8n8.x4.shared.b16 {%0,%1,%2,%3}, [%4];"
        : "=r"(r[0]), "=r"(r[1]), "=r"(r[2]), "=r"(r[3]) : "r"(addr));
}

// Warp GEMM over 80 rows (5 mt tiles): D += Xsplit @ Wsplit^T (2-term bf16 split, 3 MMAs).
template<int NT>
__device__ __forceinline__ void gemm_w(uint32_t aH, uint32_t aL, const uint4* __restrict__ bf,
                                       int nt0, int ntot, float (&acc)[5][NT][4], int lane) {
    const uint32_t ab = (lane & 15) * 128;
    const int hi4 = lane >> 4, sw = lane & 7;
#pragma unroll
    for (int mt = 0; mt < 5; mt++) {
        uint32_t Ah[4][4], Al[4][4];
#pragma unroll
        for (int ks = 0; ks < 4; ks++) {
            uint32_t off = mt * 2048 + ab + (((2 * ks + hi4) ^ sw) << 4);
            ldm4(Ah[ks], aH + off);
            ldm4(Al[ks], aL + off);
        }
#pragma unroll
        for (int j = 0; j < NT; j++) {
#pragma unroll
            for (int ks = 0; ks < 4; ks++) {
                uint4 B = bf[(ks * ntot + nt0 + j) * 32 + lane];
                mma_bf16(acc[mt][j], Ah[ks], B.x, B.y);
                mma_bf16(acc[mt][j], Al[ks], B.x, B.y);
                mma_bf16(acc[mt][j], Ah[ks], B.z, B.w);
            }
        }
    }
}

__device__ __forceinline__ uint4 mkfrag(const float* W, int rs, int n, int k) {
    uint4 r;
    uint32_t h, l;
    split2(W[n * rs + k], W[n * rs + k + 1], h, l);
    r.x = h; r.z = l;
    split2(W[n * rs + k + 8], W[n * rs + k + 9], h, l);
    r.y = h; r.w = l;
    return r;
}

// prep: weight fragments + base embedding
__global__ void prep_kernel(const float* __restrict__ Wqkv, const float* __restrict__ Wo,
                            const float* __restrict__ W1, const float* __restrict__ W2,
                            const int* __restrict__ toks, const float* __restrict__ temb,
                            const float* __restrict__ demb, const float* __restrict__ trait_b,
                            const float* __restrict__ intent_b) {
    int st = gridDim.x * blockDim.x, t0 = blockIdx.x * blockDim.x + threadIdx.x;
    for (int e = t0; e < STATE * 64; e += st) {
        int i = e >> 6, d = e & 63;
        float s = 0.f;
#pragma unroll
        for (int t = 0; t < 8; t++) s += temb[(size_t)toks[i * 8 + t] * 64 + d];
        g_base[e] = s * 0.125f + demb[e] + trait_b[d] + intent_b[d];
    }
    for (int i = t0; i < NLAY * 4 * 24 * 32; i += st) {
        int lane = i & 31, nt = (i >> 5) % 24, kt = (i >> 5) / 24 % 4, l = i / (32 * 24 * 4);
        g_qkvF[i] = mkfrag(Wqkv + l * 192 * 64, 64, nt * 8 + (lane >> 2), kt * 16 + (lane & 3) * 2);
    }
    for (int i = t0; i < NLAY * 4 * 8 * 32; i += st) {
        int lane = i & 31, nt = (i >> 5) % 8, kt = (i >> 5) / 8 % 4, l = i / (32 * 8 * 4);
        g_woF[i] = mkfrag(Wo + l * 64 * 64, 64, nt * 8 + (lane >> 2), kt * 16 + (lane & 3) * 2);
    }
    for (int i = t0; i < NLAY * 8 * 4 * 8 * 32; i += st) {
        int lane = i & 31, nt = (i >> 5) % 8, kt = (i >> 5) / 8 % 4;
        int ct = (i >> 5) / 32 % 8, l = i / (32 * 8 * 4 * 8);
        g_w1F[i] = mkfrag(W1 + l * 512 * 64, 64, ct * 64 + nt * 8 + (lane >> 2),
                          kt * 16 + (lane & 3) * 2);
    }
    for (int i = t0; i < NLAY * 8 * 4 * 8 * 32; i += st) {
        int lane = i & 31, nt = (i >> 5) % 8, kt = (i >> 5) / 8 % 4;
        int ct = (i >> 5) / 32 % 8, l = i / (32 * 8 * 4 * 8);
        g_w2F[i] = mkfrag(W2 + l * 64 * 512, 512, nt * 8 + (lane >> 2),
                          ct * 64 + kt * 16 + (lane & 3) * 2);
    }
}

__device__ __forceinline__ void ln_pass(float* ys, char* xhB, char* xlB,
                                        const float* g, const float* bb, int tid) {
    int w = tid >> 5, lane = tid & 31;
    for (int row = w; row < 80; row += 8) {
        float2 v = ((float2*)ys)[row * 32 + lane];
        float s = v.x + v.y, q = v.x * v.x + v.y * v.y;
#pragma unroll
        for (int off = 16; off; off >>= 1) {
            s += __shfl_xor_sync(0xffffffffu, s, off);
            q += __shfl_xor_sync(0xffffffffu, q, off);
        }
        float mn = s * (1.f / 64.f);
        float rs = rsqrtf(q * (1.f / 64.f) - mn * mn + 1e-5f);
        bool real = (row % 40) < 35;
        float o0 = real ? (v.x - mn) * rs * g[lane * 2] + bb[lane * 2] : 0.f;
        float o1 = real ? (v.y - mn) * rs * g[lane * 2 + 1] + bb[lane * 2 + 1] : 0.f;
        ((float2*)ys)[row * 32 + lane] = make_float2(o0, o1);
        uint32_t h, l2;
        split2(o0, o1, h, l2);
        int byte = swb(row, lane * 2);
        *(uint32_t*)(xhB + byte) = h;
        *(uint32_t*)(xlB + byte) = l2;
    }
}

__global__ void __launch_bounds__(TPB, 2)
fused_kernel(const float* __restrict__ traits, const float* __restrict__ rel,
             const float* __restrict__ memc, const float* __restrict__ trait_W,
             const float* __restrict__ intent_W, const float* __restrict__ cls,
             const float* __restrict__ bqkv, const float* __restrict__ bo,
             const float* __restrict__ ln1g, const float* __restrict__ ln1b,
             const float* __restrict__ b1, const float* __restrict__ b2,
             const float* __restrict__ ln2g, const float* __restrict__ ln2b,
             const float* __restrict__ outW, const float* __restrict__ outb,
             const float* __restrict__ outlng, const float* __restrict__ outlnb,
             float* __restrict__ out_sit, float* __restrict__ out_seq,
             float* __restrict__ out_mem) {
    extern __shared__ float smem[];
    char* xhB = (char*)(smem + XH_F);
    char* xlB = (char*)(smem + XL_F);
    char* hB  = (char*)(smem + BIG_F);   // hidden: hh0,hh1 (20480B) then hl0,hl1
    float* qkv = smem + BIG_F;
    float* ys  = smem + YS_F;

    const int tid = threadIdx.x;
    const int wid = tid >> 5, lane = tid & 31;
    const uint32_t sb = smem_u32(smem);
    const uint32_t xh_a = sb + XH_F * 4, xl_a = sb + XL_F * 4;
    const uint32_t hh_a = sb + BIG_F * 4;
    const int gb0 = blockIdx.x * 2;
    const int r0l = lane >> 2, ql = lane & 3;

    // ---- build x: ys float + xh/xl swizzled bf16 ----
    for (int idx = tid; idx < 80 * 32; idx += TPB) {
        int row = idx >> 5, cp = idx & 31;
        int slot = row / 40, lr = row % 40, gb = gb0 + slot;
        float v[2];
#pragma unroll
        for (int u = 0; u < 2; u++) {
            int d = cp * 2 + u;
            float x = 0.f;
            if (lr == 0) x = cls[d];
            else if (lr <= STATE) {
                int i = lr - 1;
                x = g_base[i * 64 + d]
                    + traits[((size_t)gb * STATE + i) * 2] * trait_W[d * 2]
                    + traits[((size_t)gb * STATE + i) * 2 + 1] * trait_W[d * 2 + 1]
                    + rel[(size_t)gb * STATE + i] * intent_W[d];
            } else if (lr < 35) {
                x = memc[((size_t)gb * MEMN + (lr - 25)) * 64 + d];
            }
            v[u] = x;
        }
        ((float2*)ys)[row * 32 + cp] = make_float2(v[0], v[1]);
        uint32_t h, l;
        split2(v[0], v[1], h, l);
        int byte = swb(row, cp * 2);
        *(uint32_t*)(xhB + byte) = h;
        *(uint32_t*)(xlB + byte) = l;
    }
    __syncthreads();

    for (int l = 0; l < NLAY; l++) {
        // ======== QKV: each warp covers 24 cols ========
        {
            float acc[5][3][4];
#pragma unroll
            for (int m = 0; m < 5; m++)
#pragma unroll
                for (int j = 0; j < 3; j++)
#pragma unroll
                    for (int c = 0; c < 4; c++) acc[m][j][c] = 0.f;
            gemm_w<3>(xh_a, xl_a, g_qkvF + l * 4 * 24 * 32, wid * 3, 24, acc, lane);
#pragma unroll
            for (int m = 0; m < 5; m++)
#pragma unroll
                for (int j = 0; j < 3; j++) {
                    int row = m * 16 + r0l;
                    int n = (wid * 3 + j) * 8 + ql * 2;
                    float2 bb = *(const float2*)(bqkv + l * 192 + n);
                    *(float2*)(qkv + row * QSTR + n) =
                        make_float2(acc[m][j][0] + bb.x, acc[m][j][1] + bb.y);
                    *(float2*)(qkv + (row + 8) * QSTR + n) =
                        make_float2(acc[m][j][2] + bb.x, acc[m][j][3] + bb.y);
                }
        }
        __syncthreads();
        // ======== attention (float4 loads) -> xh/xl ========
        for (int t = tid; t < 560; t += TPB) {
            int i = t % 35, sh = t / 35, slot = sh >> 3, h = sh & 7;
            int rb = slot * 40;
            float4 q0 = *(float4*)(qkv + (rb + i) * QSTR + h * 8);
            float4 q1 = *(float4*)(qkv + (rb + i) * QSTR + h * 8 + 4);
            float sc[35];
            float mx = -1e30f;
#pragma unroll
            for (int j = 0; j < 35; j++) {
                float4 k0 = *(float4*)(qkv + (rb + j) * QSTR + 64 + h * 8);
                float4 k1 = *(float4*)(qkv + (rb + j) * QSTR + 64 + h * 8 + 4);
                float a = q0.x * k0.x + q0.y * k0.y + q0.z * k0.z + q0.w * k0.w
                        + q1.x * k1.x + q1.y * k1.y + q1.z * k1.z + q1.w * k1.w;
                a *= 0.35355339059327373f;
                sc[j] = a;
                mx = fmaxf(mx, a);
            }
            float sum = 0.f;
#pragma unroll
            for (int j = 0; j < 35; j++) { float e = __expf(sc[j] - mx); sc[j] = e; sum += e; }
            float inv = 1.f / sum;
            float o[8];
#pragma unroll
            for (int d = 0; d < 8; d++) o[d] = 0.f;
#pragma unroll
            for (int j = 0; j < 35; j++) {
                float w = sc[j];
                float4 v0 = *(float4*)(qkv + (rb + j) * QSTR + 128 + h * 8);
                float4 v1 = *(float4*)(qkv + (rb + j) * QSTR + 128 + h * 8 + 4);
                o[0] += w * v0.x; o[1] += w * v0.y; o[2] += w * v0.z; o[3] += w * v0.w;
                o[4] += w * v1.x; o[5] += w * v1.y; o[6] += w * v1.z; o[7] += w * v1.w;
            }
            int row = rb + i;
#pragma unroll
            for (int d = 0; d < 8; d += 2) {
                uint32_t hh, ll;
                split2(o[d] * inv, o[d + 1] * inv, hh, ll);
                int byte = swb(row, h * 8 + d);
                *(uint32_t*)(xhB + byte) = hh;
                *(uint32_t*)(xlB + byte) = ll;
            }
        }
        __syncthreads();
        // ======== Wo ========
        {
            float acc[5][1][4];
#pragma unroll
            for (int m = 0; m < 5; m++)
#pragma unroll
                for (int c = 0; c < 4; c++) acc[m][0][c] = 0.f;
            gemm_w<1>(xh_a, xl_a, g_woF + l * 4 * 8 * 32, wid, 8, acc, lane);
#pragma unroll
            for (int m = 0; m < 5; m++) {
                int row = m * 16 + r0l;
                int n = wid * 8 + ql * 2;
                float2 bb = *(const float2*)(bo + l * 64 + n);
                float2 y0 = *(float2*)(ys + row * 64 + n);
                float2 y1 = *(float2*)(ys + (row + 8) * 64 + n);
                *(float2*)(ys + row * 64 + n) =
                    make_float2(y0.x + acc[m][0][0] + bb.x, y0.y + acc[m][0][1] + bb.y);
                *(float2*)(ys + (row + 8) * 64 + n) =
                    make_float2(y1.x + acc[m][0][2] + bb.x, y1.y + acc[m][0][3] + bb.y);
            }
        }
        __syncthreads();
        ln_pass(ys, xhB, xlB, ln1g + l * 64, ln1b + l * 64, tid);
        __syncthreads();
        // ======== FF: 4 chunks of 128 hidden; W2 acc in regs across chunks ========
        {
            float acc2[5][1][4];
#pragma unroll
            for (int m = 0; m < 5; m++)
#pragma unroll
                for (int c = 0; c < 4; c++) acc2[m][0][c] = 0.f;
            for (int cc = 0; cc < 4; cc++) {
                // FF1: warp covers 2 nt tiles in its ct half (wid>>2) of the 128-col chunk
                float acc1[5][2][4];
#pragma unroll
                for (int m = 0; m < 5; m++)
#pragma unroll
                    for (int j = 0; j < 2; j++)
#pragma unroll
                        for (int c = 0; c < 4; c++) acc1[m][j][c] = 0.f;
                int ct = 2 * cc + (wid >> 2);
                gemm_w<2>(xh_a, xl_a, g_w1F + (l * 8 + ct) * 1024, (wid & 3) * 2, 8, acc1, lane);
#pragma unroll
                for (int m = 0; m < 5; m++) {
#pragma unroll
                    for (int j = 0; j < 2; j++) {
                        int row = m * 16 + r0l;
                        int nt = (wid & 3) * 2 + j;
                        int colin = nt * 8 + ql * 2;
                        int img = wid >> 2;
                        int bn = l * 512 + cc * 128 + img * 64 + colin;
                        float2 bb = *(const float2*)(b1 + bn);
                        uint32_t h, lo2;
                        split2(gelu_f(acc1[m][j][0] + bb.x), gelu_f(acc1[m][j][1] + bb.y), h, lo2);
                        int byte = img * 10240 + swb(row, colin);
                        *(uint32_t*)(hB + byte) = h;
                        *(uint32_t*)(hB + 20480 + byte) = lo2;
                        split2(gelu_f(acc1[m][j][2] + bb.x), gelu_f(acc1[m][j][3] + bb.y), h, lo2);
                        byte = img * 10240 + swb(row + 8, colin);
                        *(uint32_t*)(hB + byte) = h;
                        *(uint32_t*)(hB + 20480 + byte) = lo2;
                    }
                }
                __syncthreads();
                // FF2: two 64-col K passes over the hidden images
#pragma unroll
                for (int img = 0; img < 2; img++) {
                    gemm_w<1>(hh_a + img * 10240, hh_a + 20480 + img * 10240,
                              g_w2F + (l * 8 + 2 * cc + img) * 1024, wid, 8, acc2, lane);
                }
                __syncthreads();
            }
#pragma unroll
            for (int m = 0; m < 5; m++) {
                int row = m * 16 + r0l;
                int n = wid * 8 + ql * 2;
                float2 bb = *(const float2*)(b2 + l * 64 + n);
                float2 y0 = *(float2*)(ys + row * 64 + n);
                float2 y1 = *(float2*)(ys + (row + 8) * 64 + n);
                *(float2*)(ys + row * 64 + n) =
                    make_float2(y0.x + acc2[m][0][0] + bb.x, y0.y + acc2[m][0][1] + bb.y);
                *(float2*)(ys + (row + 8) * 64 + n) =
                    make_float2(y1.x + acc2[m][0][2] + bb.x, y1.y + acc2[m][0][3] + bb.y);
            }
        }
        __syncthreads();
        ln_pass(ys, xhB, xlB, ln2g + l * 64, ln2b + l * 64, tid);
        __syncthreads();
    }

    // ---- head: situation = LN128(x[cls] @ outW^T + outb) ----
    {
        int slot = tid >> 7, j = tid & 127;
        float a = outb[j];
        const float* wr = outW + j * 64;
        const float* xr = ys + (slot * 40) * 64;
#pragma unroll
        for (int k = 0; k < 64; k++) a += xr[k] * wr[k];
        qkv[slot * 128 + j] = a;
    }
    __syncthreads();
    if (wid < 2) {
        float v4[4];
        float s = 0.f, q = 0.f;
#pragma unroll
        for (int u = 0; u < 4; u++) {
            float v = qkv[wid * 128 + lane * 4 + u];
            v4[u] = v; s += v; q += v * v;
        }
#pragma unroll
        for (int off = 16; off; off >>= 1) {
            s += __shfl_xor_sync(0xffffffffu, s, off);
            q += __shfl_xor_sync(0xffffffffu, q, off);
        }
        float mn = s * (1.f / 128.f);
        float rs = rsqrtf(q * (1.f / 128.f) - mn * mn + 1e-5f);
#pragma unroll
        for (int u = 0; u < 4; u++) {
            int j = lane * 4 + u;
            out_sit[(size_t)(gb0 + wid) * 128 + j] = (v4[u] - mn) * rs * outlng[j] + outlnb[j];
        }
    }
    for (int idx = tid; idx < 2 * STATE * 64; idx += TPB) {
        int slot = idx / (STATE * 64), r2 = idx % (STATE * 64);
        out_seq[(size_t)(gb0 + slot) * STATE * 64 + r2] =
            ys[(slot * 40 + 1 + (r2 >> 6)) * 64 + (r2 & 63)];
    }
    for (int idx = tid; idx < 2 * 9 * 64; idx += TPB) {
        int slot = idx / (9 * 64), r2 = idx % (9 * 64);
        out_mem[(size_t)(gb0 + slot) * 640 + r2] = memc[(size_t)(gb0 + slot) * 640 + 64 + r2];
    }
    if (tid < 128) {
        int slot = tid >> 6, d = tid & 63;
        float s = 0.f;
#pragma unroll
        for (int i = 1; i <= STATE; i++) s += ys[(slot * 40 + i) * 64 + d];
        out_mem[(size_t)(gb0 + slot) * 640 + 9 * 64 + d] = s * (1.f / 24.f);
    }
}

extern "C" void kernel_launch(void* const* d_in, const int* in_sizes, int n_in,
                              void* d_out, int out_size) {
    const int*   toks     = (const int*)d_in[0];
    const float* traits   = (const float*)d_in[1];
    const float* rel      = (const float*)d_in[2];
    const float* memc     = (const float*)d_in[3];
    const float* temb     = (const float*)d_in[4];
    const float* demb     = (const float*)d_in[5];
    const float* trait_W  = (const float*)d_in[6];
    const float* trait_b  = (const float*)d_in[7];
    const float* intent_W = (const float*)d_in[8];
    const float* intent_b = (const float*)d_in[9];
    const float* cls      = (const float*)d_in[10];
    const float* Wqkv     = (const float*)d_in[11];
    const float* bqkv     = (const float*)d_in[12];
    const float* Wo       = (const float*)d_in[13];
    const float* bo       = (const float*)d_in[14];
    const float* ln1g     = (const float*)d_in[15];
    const float* ln1b     = (const float*)d_in[16];
    const float* W1       = (const float*)d_in[17];
    const float* b1       = (const float*)d_in[18];
    const float* W2       = (const float*)d_in[19];
    const float* b2       = (const float*)d_in[20];
    const float* ln2g     = (const float*)d_in[21];
    const float* ln2b     = (const float*)d_in[22];
    const float* outW     = (const float*)d_in[23];
    const float* outb     = (const float*)d_in[24];
    const float* outlng   = (const float*)d_in[25];
    const float* outlnb   = (const float*)d_in[26];

    int B = in_sizes[2] / STATE;
    float* out = (float*)d_out;
    float* out_sit = out;
    float* out_seq = out + (size_t)B * 128;
    float* out_mem = out_seq + (size_t)B * STATE * 64;

    prep_kernel<<<120, 256>>>(Wqkv, Wo, W1, W2, toks, temb, demb, trait_b, intent_b);

    cudaFuncSetAttribute(fused_kernel, cudaFuncAttributeMaxDynamicSharedMemorySize, SMEM_BYTES);
    fused_kernel<<<B / 2, TPB, SMEM_BYTES>>>(
        traits, rel, memc, trait_W, intent_W, cls,
        bqkv, bo, ln1g, ln1b, b1, b2, ln2g, ln2b,
        outW, outb, outlng, outlnb,
        out_sit, out_seq, out_mem);
}